// round 16
// baseline (speedup 1.0000x reference)
#include <cuda_runtime.h>
#include <cuda_bf16.h>
#include <math.h>

#define NN   100000
#define EE   3200000
#define DIN  256
#define DHID 256
#define DOUT 64
#define NB   ((NN + 255) / 256)   // 391 scan blocks

// ---------------- scratch (__device__ globals; no allocation allowed) -------
__device__ int   g_deg[NN];
__device__ int   g_off[NN + 1];
__device__ int   g_cur[NN];
__device__ float g_dinv[NN];
__device__ int   g_csr[EE];
__device__ int   g_blk[NB];
__device__ int   g_blkoff[NB];
__device__ __align__(16) __nv_bfloat16 g_xb[(size_t)NN * DIN];   // bf16 copy of x
__device__ __align__(16) __nv_bfloat16 g_h1[(size_t)NN * DHID];  // bf16 x@W1
__device__ __align__(16) __nv_bfloat16 g_a1[(size_t)NN * DHID];  // bf16 relu(agg)
__device__ __align__(16) __nv_bfloat16 g_h2[(size_t)NN * DOUT];  // bf16 a1@W2

// ---------------- side stream for fork-join overlap (created pre-main) -------
static cudaStream_t g_s2;
static cudaEvent_t  g_evA, g_evB;
static struct SideInit {
    SideInit() {
        cudaStreamCreateWithFlags(&g_s2, cudaStreamNonBlocking);
        cudaEventCreateWithFlags(&g_evA, cudaEventDisableTiming);
        cudaEventCreateWithFlags(&g_evB, cudaEventDisableTiming);
    }
} g_side_init;

// ---------------- helpers ----------------------------------------------------
__device__ __forceinline__ unsigned int bf2(float lo, float hi) {
    unsigned int r;
    asm("cvt.rn.bf16x2.f32 %0, %1, %2;" : "=r"(r) : "f"(hi), "f"(lo));
    return r;
}
__device__ __forceinline__ float2 ubf2f(unsigned int u) {
    return __bfloat1622float2(*reinterpret_cast<const __nv_bfloat162*>(&u));
}
__device__ __forceinline__ unsigned int smem_u32(const void* p) {
    return (unsigned int)__cvta_generic_to_shared(p);
}
__device__ __forceinline__ void ldsm_x4(unsigned int addr, unsigned int& r0,
                                        unsigned int& r1, unsigned int& r2,
                                        unsigned int& r3) {
    asm volatile("ldmatrix.sync.aligned.m8n8.x4.shared.b16 {%0,%1,%2,%3}, [%4];"
                 : "=r"(r0), "=r"(r1), "=r"(r2), "=r"(r3) : "r"(addr));
}
__device__ __forceinline__ void ldsm_x4t(unsigned int addr, unsigned int& r0,
                                         unsigned int& r1, unsigned int& r2,
                                         unsigned int& r3) {
    asm volatile("ldmatrix.sync.aligned.m8n8.x4.trans.shared.b16 {%0,%1,%2,%3}, [%4];"
                 : "=r"(r0), "=r"(r1), "=r"(r2), "=r"(r3) : "r"(addr));
}
__device__ __forceinline__ void mma_bf16(float c[4],
                                         unsigned int a0, unsigned int a1,
                                         unsigned int a2, unsigned int a3,
                                         unsigned int b0, unsigned int b1) {
    asm volatile(
        "mma.sync.aligned.m16n8k16.row.col.f32.bf16.bf16.f32 "
        "{%0,%1,%2,%3},{%4,%5,%6,%7},{%8,%9},{%0,%1,%2,%3};"
        : "+f"(c[0]), "+f"(c[1]), "+f"(c[2]), "+f"(c[3])
        : "r"(a0), "r"(a1), "r"(a2), "r"(a3), "r"(b0), "r"(b1));
}

// ---------------- x fp32 -> bf16 (one-time, side stream) ----------------------
extern "C" __global__ __launch_bounds__(256) void k_cvt(const float* __restrict__ x) {
    const long long n8 = (long long)NN * DIN / 8;
    for (long long i = blockIdx.x * blockDim.x + threadIdx.x; i < n8;
         i += (long long)gridDim.x * blockDim.x) {
        float4 a = ((const float4*)x)[2 * i];
        float4 b = ((const float4*)x)[2 * i + 1];
        uint4 p;
        p.x = bf2(a.x, a.y); p.y = bf2(a.z, a.w);
        p.z = bf2(b.x, b.y); p.w = bf2(b.z, b.w);
        ((uint4*)g_xb)[i] = p;
    }
}

// ---------------- degree count (int4 edge reads) -------------------------------
extern "C" __global__ __launch_bounds__(256) void k_count(const int* dst, int e) {
    int n4 = e >> 2;
    for (int i = blockIdx.x * blockDim.x + threadIdx.x; i < n4;
         i += gridDim.x * blockDim.x) {
        int4 d = ((const int4*)dst)[i];
        atomicAdd(&g_deg[d.x], 1);
        atomicAdd(&g_deg[d.y], 1);
        atomicAdd(&g_deg[d.z], 1);
        atomicAdd(&g_deg[d.w], 1);
    }
}

// ---------------- 3-phase wide scan -------------------------------------------
extern "C" __global__ __launch_bounds__(256) void k_blksum() {
    __shared__ int wsum[8];
    int b = blockIdx.x, t = threadIdx.x;
    int lane = t & 31, wid = t >> 5;
    int i = b * 256 + t;
    int d = (i < NN) ? g_deg[i] : 0;
    int v = d;
#pragma unroll
    for (int o = 16; o; o >>= 1) v += __shfl_down_sync(0xffffffffu, v, o);
    if (lane == 0) wsum[wid] = v;
    __syncthreads();
    if (t == 0) {
        int s = 0;
#pragma unroll
        for (int q = 0; q < 8; q++) s += wsum[q];
        g_blk[b] = s;
    }
}

extern "C" __global__ __launch_bounds__(512) void k_scanblk() {
    __shared__ int sm[512];
    int t = threadIdx.x;
    int v = (t < NB) ? g_blk[t] : 0;
    sm[t] = v;
    __syncthreads();
    for (int o = 1; o < 512; o <<= 1) {
        int n = (t >= o) ? sm[t - o] : 0;
        __syncthreads();
        sm[t] += n;
        __syncthreads();
    }
    if (t < NB) g_blkoff[t] = sm[t] - v;   // exclusive
}

extern "C" __global__ __launch_bounds__(256) void k_offsets() {
    __shared__ int wsum[8];
    int b = blockIdx.x, t = threadIdx.x;
    int lane = t & 31, wid = t >> 5;
    int i = b * 256 + t;
    int d = (i < NN) ? g_deg[i] : 0;
    int v = d;
#pragma unroll
    for (int o = 1; o < 32; o <<= 1) {
        int n = __shfl_up_sync(0xffffffffu, v, o);
        if (lane >= o) v += n;
    }
    if (lane == 31) wsum[wid] = v;
    __syncthreads();
    if (wid == 0 && lane < 8) {
        int x = wsum[lane];
#pragma unroll
        for (int o = 1; o < 8; o <<= 1) {
            int n = __shfl_up_sync(0xffu, x, o);
            if (lane >= o) x += n;
        }
        wsum[lane] = x;
    }
    __syncthreads();
    int base = g_blkoff[b] + ((wid > 0) ? wsum[wid - 1] : 0) + (v - d);
    if (i < NN) {
        g_off[i]  = base;
        g_cur[i]  = base;
        g_dinv[i] = rsqrtf((float)(d + 1));
        if (i == NN - 1) g_off[NN] = base + d;
    }
}

extern "C" __global__ __launch_bounds__(256) void k_fill(const int* src,
                                                         const int* dst, int e) {
    int n4 = e >> 2;
    for (int i = blockIdx.x * blockDim.x + threadIdx.x; i < n4;
         i += gridDim.x * blockDim.x) {
        int4 s = ((const int4*)src)[i];
        int4 d = ((const int4*)dst)[i];
        g_csr[atomicAdd(&g_cur[d.x], 1)] = s.x;
        g_csr[atomicAdd(&g_cur[d.y], 1)] = s.y;
        g_csr[atomicAdd(&g_cur[d.z], 1)] = s.z;
        g_csr[atomicAdd(&g_cur[d.w], 1)] = s.w;
    }
}

// ---------------- GEMM 1 (tensor core, bf16 A, 2 CTAs/SM) --------------------
// g_h1(bf16) = xb(bf16) @ W1. BM=128, BN=128, BK=16, 256 thr, 8 warps,
// warp tile 64x32, double-buffered, 1 sync/iter.
#define AP1 24
#define BP1 136
extern "C" __global__ __launch_bounds__(256, 2) void k_gemm1(
    const float* __restrict__ B) {
    __shared__ __align__(16) __nv_bfloat16 Asm[2][128 * AP1];
    __shared__ __align__(16) __nv_bfloat16 Bsm[2][16 * BP1];
    const int tid  = threadIdx.x;
    const int wid  = tid >> 5;
    const int lane = tid & 31;
    const int bx   = blockIdx.x & 1;
    const int by   = blockIdx.x >> 1;
    const int m0   = by * 128;
    const int n0   = bx * 128;
    const int wm   = (wid & 1) * 64;
    const int wn   = (wid >> 1) * 32;

    const int a_row  = tid >> 1;              // 0..127
    const int a_half = (tid & 1) * 8;         // 0 or 8 (8 bf16 = uint4)
    const int b_kr   = tid >> 4;              // 0..15
    const int b_nc   = (tid & 15) * 8;        // 0..120

    float c[4][4][4];
#pragma unroll
    for (int i = 0; i < 4; i++)
#pragma unroll
        for (int j = 0; j < 4; j++)
#pragma unroll
            for (int q = 0; q < 4; q++) c[i][j][q] = 0.f;

    const int NK = DIN / 16;

    uint4 va;
    float4 vb0, vb1;
    {
        int gm = m0 + a_row;
        va = make_uint4(0u, 0u, 0u, 0u);
        if (gm < NN) va = *(const uint4*)(g_xb + (size_t)gm * DIN + a_half);
        const float* bp = B + (size_t)b_kr * DHID + n0 + b_nc;
        vb0 = *(const float4*)bp;
        vb1 = *(const float4*)(bp + 4);
    }
    {
        *(uint4*)&Asm[0][a_row * AP1 + a_half] = va;
        __nv_bfloat16* bs = &Bsm[0][b_kr * BP1 + b_nc];
        *(uint2*)bs       = make_uint2(bf2(vb0.x, vb0.y), bf2(vb0.z, vb0.w));
        *(uint2*)(bs + 4) = make_uint2(bf2(vb1.x, vb1.y), bf2(vb1.z, vb1.w));
    }
    __syncthreads();

    for (int k = 0; k < NK; k++) {
        int cur = k & 1;
        if (k + 1 < NK) {
            int k0 = (k + 1) * 16;
            int gm = m0 + a_row;
            va = make_uint4(0u, 0u, 0u, 0u);
            if (gm < NN) va = *(const uint4*)(g_xb + (size_t)gm * DIN + k0 + a_half);
            const float* bp = B + (size_t)(k0 + b_kr) * DHID + n0 + b_nc;
            vb0 = *(const float4*)bp;
            vb1 = *(const float4*)(bp + 4);
        }

        unsigned int a[4][4];
#pragma unroll
        for (int ms = 0; ms < 4; ms++) {
            int row = wm + ms * 16 + (lane & 15);
            int col = (lane >> 4) * 8;
            ldsm_x4(smem_u32(&Asm[cur][row * AP1 + col]),
                    a[ms][0], a[ms][1], a[ms][2], a[ms][3]);
        }
        unsigned int b[4][2];
#pragma unroll
        for (int nt = 0; nt < 2; nt++) {
            int kk = lane & 15;
            int nb = wn + nt * 16 + (lane >> 4) * 8;
            ldsm_x4t(smem_u32(&Bsm[cur][kk * BP1 + nb]),
                     b[2 * nt][0], b[2 * nt][1], b[2 * nt + 1][0], b[2 * nt + 1][1]);
        }
#pragma unroll
        for (int ms = 0; ms < 4; ms++)
#pragma unroll
            for (int ns = 0; ns < 4; ns++)
                mma_bf16(c[ms][ns], a[ms][0], a[ms][1], a[ms][2], a[ms][3],
                         b[ns][0], b[ns][1]);

        if (k + 1 < NK) {
            int nxt = cur ^ 1;
            *(uint4*)&Asm[nxt][a_row * AP1 + a_half] = va;
            __nv_bfloat16* bs = &Bsm[nxt][b_kr * BP1 + b_nc];
            *(uint2*)bs       = make_uint2(bf2(vb0.x, vb0.y), bf2(vb0.z, vb0.w));
            *(uint2*)(bs + 4) = make_uint2(bf2(vb1.x, vb1.y), bf2(vb1.z, vb1.w));
        }
        __syncthreads();
    }

#pragma unroll
    for (int ms = 0; ms < 4; ms++) {
        int r0 = m0 + wm + ms * 16 + (lane >> 2);
        int r1 = r0 + 8;
#pragma unroll
        for (int ns = 0; ns < 4; ns++) {
            int col = n0 + wn + ns * 8 + (lane & 3) * 2;
            if (r0 < NN)
                *(unsigned int*)(g_h1 + (size_t)r0 * DHID + col) =
                    bf2(c[ms][ns][0], c[ms][ns][1]);
            if (r1 < NN)
                *(unsigned int*)(g_h1 + (size_t)r1 * DHID + col) =
                    bf2(c[ms][ns][2], c[ms][ns][3]);
        }
    }
}

// ---------------- GEMM 2 (tensor core): g_h2(bf16) = g_a1(bf16) @ W2 ---------
#define BP2 72
extern "C" __global__ __launch_bounds__(128) void k_gemm2(
    const float* __restrict__ B) {
    __shared__ __align__(16) __nv_bfloat16 Asm[128 * AP1];
    __shared__ __align__(16) __nv_bfloat16 Bsm[16 * BP2];
    const int tid  = threadIdx.x;
    const int wid  = tid >> 5;
    const int lane = tid & 31;
    const int m0   = blockIdx.x * 128;
    const int wm   = (wid & 1) * 64;
    const int wn   = (wid >> 1) * 32;

    float c[4][4][4];
#pragma unroll
    for (int i = 0; i < 4; i++)
#pragma unroll
        for (int j = 0; j < 4; j++)
#pragma unroll
            for (int q = 0; q < 4; q++) c[i][j][q] = 0.f;

    for (int k0 = 0; k0 < DHID; k0 += 16) {
#pragma unroll
        for (int i = 0; i < 2; i++) {
            int idx  = tid + i * 128;
            int row  = idx >> 1;
            int half = (idx & 1) * 8;
            int gm   = m0 + row;
            uint4 v = make_uint4(0u, 0u, 0u, 0u);
            if (gm < NN) v = *(const uint4*)(g_a1 + (size_t)gm * DHID + k0 + half);
            *(uint4*)&Asm[row * AP1 + half] = v;
        }
#pragma unroll
        for (int i = 0; i < 2; i++) {
            int idx = tid + i * 128;
            int kr  = idx >> 4;
            int nc  = (idx & 15) * 4;
            float4 v = *(const float4*)(B + (size_t)(k0 + kr) * DOUT + nc);
            *(uint2*)&Bsm[kr * BP2 + nc] = make_uint2(bf2(v.x, v.y), bf2(v.z, v.w));
        }
        __syncthreads();

        unsigned int a[4][4];
#pragma unroll
        for (int ms = 0; ms < 4; ms++) {
            int row = wm + ms * 16 + (lane & 15);
            int col = (lane >> 4) * 8;
            ldsm_x4(smem_u32(&Asm[row * AP1 + col]),
                    a[ms][0], a[ms][1], a[ms][2], a[ms][3]);
        }
        unsigned int b[4][2];
#pragma unroll
        for (int nt = 0; nt < 2; nt++) {
            int k  = lane & 15;
            int nb = wn + nt * 16 + (lane >> 4) * 8;
            ldsm_x4t(smem_u32(&Bsm[k * BP2 + nb]),
                     b[2 * nt][0], b[2 * nt][1], b[2 * nt + 1][0], b[2 * nt + 1][1]);
        }
#pragma unroll
        for (int ms = 0; ms < 4; ms++)
#pragma unroll
            for (int ns = 0; ns < 4; ns++)
                mma_bf16(c[ms][ns], a[ms][0], a[ms][1], a[ms][2], a[ms][3],
                         b[ns][0], b[ns][1]);
        __syncthreads();
    }
#pragma unroll
    for (int ms = 0; ms < 4; ms++) {
        int r0 = m0 + wm + ms * 16 + (lane >> 2);
        int r1 = r0 + 8;
#pragma unroll
        for (int ns = 0; ns < 4; ns++) {
            int col = wn + ns * 8 + (lane & 3) * 2;
            if (r0 < NN)
                *(unsigned int*)(g_h2 + (size_t)r0 * DOUT + col) =
                    bf2(c[ms][ns][0], c[ms][ns][1]);
            if (r1 < NN)
                *(unsigned int*)(g_h2 + (size_t)r1 * DOUT + col) =
                    bf2(c[ms][ns][2], c[ms][ns][3]);
        }
    }
}

// ---------------- layer-1 aggregation: one warp per dst, unroll-8 ------------
__device__ __forceinline__ void acc_row1(float acc[8], float ws, uint4 v) {
    const unsigned int* u = (const unsigned int*)&v;
#pragma unroll
    for (int q = 0; q < 4; q++) {
        float2 f = ubf2f(u[q]);
        acc[2 * q]     = fmaf(ws, f.x, acc[2 * q]);
        acc[2 * q + 1] = fmaf(ws, f.y, acc[2 * q + 1]);
    }
}

extern "C" __global__ __launch_bounds__(256) void k_agg1(const float* __restrict__ b1) {
    int lane = threadIdx.x & 31;
    int warps = (gridDim.x * blockDim.x) >> 5;
    for (int w = (blockIdx.x * blockDim.x + threadIdx.x) >> 5; w < NN; w += warps) {
        float di = g_dinv[w];
        float acc[8];
        {
            uint4 v = __ldg(&((const uint4*)(g_h1 + (size_t)w * DHID))[lane]);
            const unsigned int* u = (const unsigned int*)&v;
#pragma unroll
            for (int q = 0; q < 4; q++) {
                float2 f = ubf2f(u[q]);
                acc[2 * q]     = di * f.x;
                acc[2 * q + 1] = di * f.y;
            }
        }
        int e   = g_off[w];
        int end = g_off[w + 1];
        for (; e + 8 <= end; e += 8) {
            int s0 = __ldg(&g_csr[e]);
            int s1 = __ldg(&g_csr[e + 1]);
            int s2 = __ldg(&g_csr[e + 2]);
            int s3 = __ldg(&g_csr[e + 3]);
            int s4 = __ldg(&g_csr[e + 4]);
            int s5 = __ldg(&g_csr[e + 5]);
            int s6 = __ldg(&g_csr[e + 6]);
            int s7 = __ldg(&g_csr[e + 7]);
            float w0 = __ldg(&g_dinv[s0]);
            float w1 = __ldg(&g_dinv[s1]);
            float w2 = __ldg(&g_dinv[s2]);
            float w3 = __ldg(&g_dinv[s3]);
            float w4 = __ldg(&g_dinv[s4]);
            float w5 = __ldg(&g_dinv[s5]);
            float w6 = __ldg(&g_dinv[s6]);
            float w7 = __ldg(&g_dinv[s7]);
            uint4 v0 = __ldg(&((const uint4*)(g_h1 + (size_t)s0 * DHID))[lane]);
            uint4 v1 = __ldg(&((const uint4*)(g_h1 + (size_t)s1 * DHID))[lane]);
            uint4 v2 = __ldg(&((const uint4*)(g_h1 + (size_t)s2 * DHID))[lane]);
            uint4 v3 = __ldg(&((const uint4*)(g_h1 + (size_t)s3 * DHID))[lane]);
            uint4 v4 = __ldg(&((const uint4*)(g_h1 + (size_t)s4 * DHID))[lane]);
            uint4 v5 = __ldg(&((const uint4*)(g_h1 + (size_t)s5 * DHID))[lane]);
            uint4 v6 = __ldg(&((const uint4*)(g_h1 + (size_t)s6 * DHID))[lane]);
            uint4 v7 = __ldg(&((const uint4*)(g_h1 + (size_t)s7 * DHID))[lane]);
            acc_row1(acc, w0, v0);
            acc_row1(acc, w1, v1);
            acc_row1(acc, w2, v2);
            acc_row1(acc, w3, v3);
            acc_row1(acc, w4, v4);
            acc_row1(acc, w5, v5);
            acc_row1(acc, w6, v6);
            acc_row1(acc, w7, v7);
        }
        for (; e + 4 <= end; e += 4) {
            int s0 = __ldg(&g_csr[e]);
            int s1 = __ldg(&g_csr[e + 1]);
            int s2 = __ldg(&g_csr[e + 2]);
            int s3 = __ldg(&g_csr[e + 3]);
            float w0 = __ldg(&g_dinv[s0]);
            float w1 = __ldg(&g_dinv[s1]);
            float w2 = __ldg(&g_dinv[s2]);
            float w3 = __ldg(&g_dinv[s3]);
            uint4 v0 = __ldg(&((const uint4*)(g_h1 + (size_t)s0 * DHID))[lane]);
            uint4 v1 = __ldg(&((const uint4*)(g_h1 + (size_t)s1 * DHID))[lane]);
            uint4 v2 = __ldg(&((const uint4*)(g_h1 + (size_t)s2 * DHID))[lane]);
            uint4 v3 = __ldg(&((const uint4*)(g_h1 + (size_t)s3 * DHID))[lane]);
            acc_row1(acc, w0, v0);
            acc_row1(acc, w1, v1);
            acc_row1(acc, w2, v2);
            acc_row1(acc, w3, v3);
        }
        for (; e < end; e++) {
            int   s  = __ldg(&g_csr[e]);
            float ws = __ldg(&g_dinv[s]);
            uint4 v  = __ldg(&((const uint4*)(g_h1 + (size_t)s * DHID))[lane]);
            acc_row1(acc, ws, v);
        }
        float4 bb0 = ((const float4*)b1)[lane * 2];
        float4 bb1 = ((const float4*)b1)[lane * 2 + 1];
        uint4 pk;
        pk.x = bf2(fmaxf(di * acc[0] + bb0.x, 0.f), fmaxf(di * acc[1] + bb0.y, 0.f));
        pk.y = bf2(fmaxf(di * acc[2] + bb0.z, 0.f), fmaxf(di * acc[3] + bb0.w, 0.f));
        pk.z = bf2(fmaxf(di * acc[4] + bb1.x, 0.f), fmaxf(di * acc[5] + bb1.y, 0.f));
        pk.w = bf2(fmaxf(di * acc[6] + bb1.z, 0.f), fmaxf(di * acc[7] + bb1.w, 0.f));
        ((uint4*)(g_a1 + (size_t)w * DHID))[lane] = pk;
    }
}

// ---------------- layer-2 aggregation + bias + log_softmax, unroll-8 ---------
extern "C" __global__ __launch_bounds__(256) void k_agg2(const float* __restrict__ b2,
                                                         float* __restrict__ out) {
    int lane = threadIdx.x & 31;
    int warps = (gridDim.x * blockDim.x) >> 5;
    for (int w = (blockIdx.x * blockDim.x + threadIdx.x) >> 5; w < NN; w += warps) {
        float di = g_dinv[w];
        float ax, ay;
        {
            unsigned int v = __ldg(&((const unsigned int*)(g_h2 + (size_t)w * DOUT))[lane]);
            float2 f = ubf2f(v);
            ax = di * f.x;
            ay = di * f.y;
        }
        int e   = g_off[w];
        int end = g_off[w + 1];
        for (; e + 8 <= end; e += 8) {
            int s0 = __ldg(&g_csr[e]);
            int s1 = __ldg(&g_csr[e + 1]);
            int s2 = __ldg(&g_csr[e + 2]);
            int s3 = __ldg(&g_csr[e + 3]);
            int s4 = __ldg(&g_csr[e + 4]);
            int s5 = __ldg(&g_csr[e + 5]);
            int s6 = __ldg(&g_csr[e + 6]);
            int s7 = __ldg(&g_csr[e + 7]);
            float w0 = __ldg(&g_dinv[s0]);
            float w1 = __ldg(&g_dinv[s1]);
            float w2 = __ldg(&g_dinv[s2]);
            float w3 = __ldg(&g_dinv[s3]);
            float w4 = __ldg(&g_dinv[s4]);
            float w5 = __ldg(&g_dinv[s5]);
            float w6 = __ldg(&g_dinv[s6]);
            float w7 = __ldg(&g_dinv[s7]);
            unsigned int v0 = __ldg(&((const unsigned int*)(g_h2 + (size_t)s0 * DOUT))[lane]);
            unsigned int v1 = __ldg(&((const unsigned int*)(g_h2 + (size_t)s1 * DOUT))[lane]);
            unsigned int v2 = __ldg(&((const unsigned int*)(g_h2 + (size_t)s2 * DOUT))[lane]);
            unsigned int v3 = __ldg(&((const unsigned int*)(g_h2 + (size_t)s3 * DOUT))[lane]);
            unsigned int v4 = __ldg(&((const unsigned int*)(g_h2 + (size_t)s4 * DOUT))[lane]);
            unsigned int v5 = __ldg(&((const unsigned int*)(g_h2 + (size_t)s5 * DOUT))[lane]);
            unsigned int v6 = __ldg(&((const unsigned int*)(g_h2 + (size_t)s6 * DOUT))[lane]);
            unsigned int v7 = __ldg(&((const unsigned int*)(g_h2 + (size_t)s7 * DOUT))[lane]);
            float2 f0 = ubf2f(v0), f1 = ubf2f(v1), f2 = ubf2f(v2), f3 = ubf2f(v3);
            float2 f4 = ubf2f(v4), f5 = ubf2f(v5), f6 = ubf2f(v6), f7 = ubf2f(v7);
            ax = fmaf(w0, f0.x, ax); ay = fmaf(w0, f0.y, ay);
            ax = fmaf(w1, f1.x, ax); ay = fmaf(w1, f1.y, ay);
            ax = fmaf(w2, f2.x, ax); ay = fmaf(w2, f2.y, ay);
            ax = fmaf(w3, f3.x, ax); ay = fmaf(w3, f3.y, ay);
            ax = fmaf(w4, f4.x, ax); ay = fmaf(w4, f4.y, ay);
            ax = fmaf(w5, f5.x, ax); ay = fmaf(w5, f5.y, ay);
            ax = fmaf(w6, f6.x, ax); ay = fmaf(w6, f6.y, ay);
            ax = fmaf(w7, f7.x, ax); ay = fmaf(w7, f7.y, ay);
        }
        for (; e < end; e++) {
            int   s  = __ldg(&g_csr[e]);
            float ws = __ldg(&g_dinv[s]);
            unsigned int v = __ldg(&((const unsigned int*)(g_h2 + (size_t)s * DOUT))[lane]);
            float2 f = ubf2f(v);
            ax = fmaf(ws, f.x, ax);
            ay = fmaf(ws, f.y, ay);
        }
        float2 bb = ((const float2*)b2)[lane];
        float zx = di * ax + bb.x;
        float zy = di * ay + bb.y;
        float m = fmaxf(zx, zy);
#pragma unroll
        for (int o = 16; o; o >>= 1) m = fmaxf(m, __shfl_xor_sync(0xffffffffu, m, o));
        float s = expf(zx - m) + expf(zy - m);
#pragma unroll
        for (int o = 16; o; o >>= 1) s += __shfl_xor_sync(0xffffffffu, s, o);
        float lse = m + logf(s);
        float2 r; r.x = zx - lse; r.y = zy - lse;
        ((float2*)(out + (size_t)w * DOUT))[lane] = r;
    }
}

// ---------------- launch ------------------------------------------------------
extern "C" void kernel_launch(void* const* d_in, const int* in_sizes, int n_in,
                              void* d_out, int out_size) {
    const float* x  = nullptr;
    const int*   ei = nullptr;
    const float* W1 = nullptr;
    const float* b1 = nullptr;
    const float* W2 = nullptr;
    const float* b2 = nullptr;
    for (int i = 0; i < n_in; i++) {
        switch (in_sizes[i]) {
            case NN * DIN:    x  = (const float*)d_in[i]; break;
            case 2 * EE:      ei = (const int*)d_in[i];   break;
            case DIN * DHID:  W1 = (const float*)d_in[i]; break;
            case DHID:        b1 = (const float*)d_in[i]; break;
            case DHID * DOUT: W2 = (const float*)d_in[i]; break;
            case DOUT:        b2 = (const float*)d_in[i]; break;
            default: break;
        }
    }
    float* out = (float*)d_out;
    const int* src = ei;
    const int* dst = ei + EE;

    int* p_deg;  cudaGetSymbolAddress((void**)&p_deg, g_deg);

    // fork: x->bf16 convert + gemm1 on side stream; CSR on main stream
    cudaEventRecord(g_evA, 0);
    cudaStreamWaitEvent(g_s2, g_evA, 0);
    k_cvt<<<2048, 256, 0, g_s2>>>(x);
    k_gemm1<<<2 * ((NN + 127) / 128), 256, 0, g_s2>>>(W1);
    cudaEventRecord(g_evB, g_s2);

    cudaMemsetAsync(p_deg, 0, NN * sizeof(int));
    k_count<<<2048, 256>>>(dst, EE);
    k_blksum<<<NB, 256>>>();
    k_scanblk<<<1, 512>>>();
    k_offsets<<<NB, 256>>>();
    k_fill<<<2048, 256>>>(src, dst, EE);

    // join: agg1 needs both gemm1 (h1) and CSR
    cudaStreamWaitEvent(0, g_evB, 0);
    k_agg1<<<12500, 256>>>(b1);

    // layer 2
    k_gemm2<<<(NN + 127) / 128, 128>>>(W2);
    k_agg2<<<12500, 256>>>(b2, out);
}

// round 17
// speedup vs baseline: 1.0145x; 1.0145x over previous
#include <cuda_runtime.h>
#include <cuda_bf16.h>
#include <math.h>

#define NN    100000
#define EE    3200000
#define DIN   256
#define DHID  256
#define DOUT  64
#define NB2   ((NN + 511) / 512)   // 196 scan chunks
#define SPLIT 50048                 // 391 * 128, M split for agg1/gemm2 overlap

// ---------------- scratch (__device__ globals; no allocation allowed) -------
__device__ int   g_deg[NN];
__device__ int   g_off[NN + 1];
__device__ int   g_cur[NN];
__device__ float g_dinv[NN];
__device__ int   g_csr[EE];
__device__ int   g_blk[NB2];
__device__ __align__(16) __nv_bfloat16 g_xb[(size_t)NN * DIN];   // bf16 copy of x
__device__ __align__(16) __nv_bfloat16 g_h1[(size_t)NN * DHID];  // bf16 x@W1
__device__ __align__(16) __nv_bfloat16 g_a1[(size_t)NN * DHID];  // bf16 relu(agg)
__device__ __align__(16) __nv_bfloat16 g_h2[(size_t)NN * DOUT];  // bf16 a1@W2

// ---------------- side stream + events (created pre-main) --------------------
static cudaStream_t g_s2;
static cudaEvent_t  g_evA, g_evB, g_evC, g_evD;
static struct SideInit {
    SideInit() {
        cudaStreamCreateWithFlags(&g_s2, cudaStreamNonBlocking);
        cudaEventCreateWithFlags(&g_evA, cudaEventDisableTiming);
        cudaEventCreateWithFlags(&g_evB, cudaEventDisableTiming);
        cudaEventCreateWithFlags(&g_evC, cudaEventDisableTiming);
        cudaEventCreateWithFlags(&g_evD, cudaEventDisableTiming);
    }
} g_side_init;

// ---------------- helpers ----------------------------------------------------
__device__ __forceinline__ unsigned int bf2(float lo, float hi) {
    unsigned int r;
    asm("cvt.rn.bf16x2.f32 %0, %1, %2;" : "=r"(r) : "f"(hi), "f"(lo));
    return r;
}
__device__ __forceinline__ float2 ubf2f(unsigned int u) {
    return __bfloat1622float2(*reinterpret_cast<const __nv_bfloat162*>(&u));
}
__device__ __forceinline__ unsigned int smem_u32(const void* p) {
    return (unsigned int)__cvta_generic_to_shared(p);
}
__device__ __forceinline__ void ldsm_x4(unsigned int addr, unsigned int& r0,
                                        unsigned int& r1, unsigned int& r2,
                                        unsigned int& r3) {
    asm volatile("ldmatrix.sync.aligned.m8n8.x4.shared.b16 {%0,%1,%2,%3}, [%4];"
                 : "=r"(r0), "=r"(r1), "=r"(r2), "=r"(r3) : "r"(addr));
}
__device__ __forceinline__ void ldsm_x4t(unsigned int addr, unsigned int& r0,
                                         unsigned int& r1, unsigned int& r2,
                                         unsigned int& r3) {
    asm volatile("ldmatrix.sync.aligned.m8n8.x4.trans.shared.b16 {%0,%1,%2,%3}, [%4];"
                 : "=r"(r0), "=r"(r1), "=r"(r2), "=r"(r3) : "r"(addr));
}
__device__ __forceinline__ void mma_bf16(float c[4],
                                         unsigned int a0, unsigned int a1,
                                         unsigned int a2, unsigned int a3,
                                         unsigned int b0, unsigned int b1) {
    asm volatile(
        "mma.sync.aligned.m16n8k16.row.col.f32.bf16.bf16.f32 "
        "{%0,%1,%2,%3},{%4,%5,%6,%7},{%8,%9},{%0,%1,%2,%3};"
        : "+f"(c[0]), "+f"(c[1]), "+f"(c[2]), "+f"(c[3])
        : "r"(a0), "r"(a1), "r"(a2), "r"(a3), "r"(b0), "r"(b1));
}

// ---------------- x fp32 -> bf16 (side stream) --------------------------------
extern "C" __global__ __launch_bounds__(256) void k_cvt(const float* __restrict__ x) {
    const long long n8 = (long long)NN * DIN / 8;
    for (long long i = blockIdx.x * blockDim.x + threadIdx.x; i < n8;
         i += (long long)gridDim.x * blockDim.x) {
        float4 a = ((const float4*)x)[2 * i];
        float4 b = ((const float4*)x)[2 * i + 1];
        uint4 p;
        p.x = bf2(a.x, a.y); p.y = bf2(a.z, a.w);
        p.z = bf2(b.x, b.y); p.w = bf2(b.z, b.w);
        ((uint4*)g_xb)[i] = p;
    }
}

// ---------------- degree count (int4 edge reads) -------------------------------
extern "C" __global__ __launch_bounds__(256) void k_count(const int* dst, int e) {
    int n4 = e >> 2;
    for (int i = blockIdx.x * blockDim.x + threadIdx.x; i < n4;
         i += gridDim.x * blockDim.x) {
        int4 d = ((const int4*)dst)[i];
        atomicAdd(&g_deg[d.x], 1);
        atomicAdd(&g_deg[d.y], 1);
        atomicAdd(&g_deg[d.z], 1);
        atomicAdd(&g_deg[d.w], 1);
    }
}

// ---------------- 2-phase wide scan (512-wide chunks) -------------------------
// phase 1: per-512-chunk sums
extern "C" __global__ __launch_bounds__(512) void k_blksum() {
    __shared__ int wsum[16];
    int b = blockIdx.x, t = threadIdx.x;
    int lane = t & 31, wid = t >> 5;
    int i = b * 512 + t;
    int d = (i < NN) ? g_deg[i] : 0;
    int v = d;
#pragma unroll
    for (int o = 16; o; o >>= 1) v += __shfl_down_sync(0xffffffffu, v, o);
    if (lane == 0) wsum[wid] = v;
    __syncthreads();
    if (t == 0) {
        int s = 0;
#pragma unroll
        for (int q = 0; q < 16; q++) s += wsum[q];
        g_blk[b] = s;
    }
}

// phase 2: every block redundantly scans the 196 chunk sums in smem, then does
// its local 512-element scan; writes offsets + cursors + dinv.
extern "C" __global__ __launch_bounds__(512) void k_offsets() {
    __shared__ int bsm[256];
    __shared__ int wsum[16];
    int b = blockIdx.x, t = threadIdx.x;
    int lane = t & 31, wid = t >> 5;

    // scan chunk sums (196 padded to 256), Hillis-Steele
    if (t < 256) bsm[t] = (t < NB2) ? g_blk[t] : 0;
    __syncthreads();
    for (int o = 1; o < 256; o <<= 1) {
        int n = (t >= o && t < 256) ? bsm[t - o] : 0;
        __syncthreads();
        if (t < 256) bsm[t] += n;
        __syncthreads();
    }
    int blkbase = (b > 0) ? bsm[b - 1] : 0;

    // local scan of 512 elements
    int i = b * 512 + t;
    int d = (i < NN) ? g_deg[i] : 0;
    int v = d;
#pragma unroll
    for (int o = 1; o < 32; o <<= 1) {
        int n = __shfl_up_sync(0xffffffffu, v, o);
        if (lane >= o) v += n;
    }
    if (lane == 31) wsum[wid] = v;
    __syncthreads();
    if (wid == 0 && lane < 16) {
        int x = wsum[lane];
#pragma unroll
        for (int o = 1; o < 16; o <<= 1) {
            int n = __shfl_up_sync(0xffffu, x, o);
            if (lane >= o) x += n;
        }
        wsum[lane] = x;
    }
    __syncthreads();
    int base = blkbase + ((wid > 0) ? wsum[wid - 1] : 0) + (v - d);
    if (i < NN) {
        g_off[i]  = base;
        g_cur[i]  = base;
        g_dinv[i] = rsqrtf((float)(d + 1));
        if (i == NN - 1) g_off[NN] = base + d;
    }
}

extern "C" __global__ __launch_bounds__(256) void k_fill(const int* src,
                                                         const int* dst, int e) {
    int n4 = e >> 2;
    for (int i = blockIdx.x * blockDim.x + threadIdx.x; i < n4;
         i += gridDim.x * blockDim.x) {
        int4 s = ((const int4*)src)[i];
        int4 d = ((const int4*)dst)[i];
        g_csr[atomicAdd(&g_cur[d.x], 1)] = s.x;
        g_csr[atomicAdd(&g_cur[d.y], 1)] = s.y;
        g_csr[atomicAdd(&g_cur[d.z], 1)] = s.z;
        g_csr[atomicAdd(&g_cur[d.w], 1)] = s.w;
    }
}

// ---------------- GEMM 1 (tensor core, bf16 A, 2 CTAs/SM) --------------------
#define AP1 24
#define BP1 136
extern "C" __global__ __launch_bounds__(256, 2) void k_gemm1(
    const float* __restrict__ B) {
    __shared__ __align__(16) __nv_bfloat16 Asm[2][128 * AP1];
    __shared__ __align__(16) __nv_bfloat16 Bsm[2][16 * BP1];
    const int tid  = threadIdx.x;
    const int wid  = tid >> 5;
    const int lane = tid & 31;
    const int bx   = blockIdx.x & 1;
    const int by   = blockIdx.x >> 1;
    const int m0   = by * 128;
    const int n0   = bx * 128;
    const int wm   = (wid & 1) * 64;
    const int wn   = (wid >> 1) * 32;

    const int a_row  = tid >> 1;
    const int a_half = (tid & 1) * 8;
    const int b_kr   = tid >> 4;
    const int b_nc   = (tid & 15) * 8;

    float c[4][4][4];
#pragma unroll
    for (int i = 0; i < 4; i++)
#pragma unroll
        for (int j = 0; j < 4; j++)
#pragma unroll
            for (int q = 0; q < 4; q++) c[i][j][q] = 0.f;

    const int NK = DIN / 16;

    uint4 va;
    float4 vb0, vb1;
    {
        int gm = m0 + a_row;
        va = make_uint4(0u, 0u, 0u, 0u);
        if (gm < NN) va = *(const uint4*)(g_xb + (size_t)gm * DIN + a_half);
        const float* bp = B + (size_t)b_kr * DHID + n0 + b_nc;
        vb0 = *(const float4*)bp;
        vb1 = *(const float4*)(bp + 4);
    }
    {
        *(uint4*)&Asm[0][a_row * AP1 + a_half] = va;
        __nv_bfloat16* bs = &Bsm[0][b_kr * BP1 + b_nc];
        *(uint2*)bs       = make_uint2(bf2(vb0.x, vb0.y), bf2(vb0.z, vb0.w));
        *(uint2*)(bs + 4) = make_uint2(bf2(vb1.x, vb1.y), bf2(vb1.z, vb1.w));
    }
    __syncthreads();

    for (int k = 0; k < NK; k++) {
        int cur = k & 1;
        if (k + 1 < NK) {
            int k0 = (k + 1) * 16;
            int gm = m0 + a_row;
            va = make_uint4(0u, 0u, 0u, 0u);
            if (gm < NN) va = *(const uint4*)(g_xb + (size_t)gm * DIN + k0 + a_half);
            const float* bp = B + (size_t)(k0 + b_kr) * DHID + n0 + b_nc;
            vb0 = *(const float4*)bp;
            vb1 = *(const float4*)(bp + 4);
        }

        unsigned int a[4][4];
#pragma unroll
        for (int ms = 0; ms < 4; ms++) {
            int row = wm + ms * 16 + (lane & 15);
            int col = (lane >> 4) * 8;
            ldsm_x4(smem_u32(&Asm[cur][row * AP1 + col]),
                    a[ms][0], a[ms][1], a[ms][2], a[ms][3]);
        }
        unsigned int b[4][2];
#pragma unroll
        for (int nt = 0; nt < 2; nt++) {
            int kk = lane & 15;
            int nb = wn + nt * 16 + (lane >> 4) * 8;
            ldsm_x4t(smem_u32(&Bsm[cur][kk * BP1 + nb]),
                     b[2 * nt][0], b[2 * nt][1], b[2 * nt + 1][0], b[2 * nt + 1][1]);
        }
#pragma unroll
        for (int ms = 0; ms < 4; ms++)
#pragma unroll
            for (int ns = 0; ns < 4; ns++)
                mma_bf16(c[ms][ns], a[ms][0], a[ms][1], a[ms][2], a[ms][3],
                         b[ns][0], b[ns][1]);

        if (k + 1 < NK) {
            int nxt = cur ^ 1;
            *(uint4*)&Asm[nxt][a_row * AP1 + a_half] = va;
            __nv_bfloat16* bs = &Bsm[nxt][b_kr * BP1 + b_nc];
            *(uint2*)bs       = make_uint2(bf2(vb0.x, vb0.y), bf2(vb0.z, vb0.w));
            *(uint2*)(bs + 4) = make_uint2(bf2(vb1.x, vb1.y), bf2(vb1.z, vb1.w));
        }
        __syncthreads();
    }

#pragma unroll
    for (int ms = 0; ms < 4; ms++) {
        int r0 = m0 + wm + ms * 16 + (lane >> 2);
        int r1 = r0 + 8;
#pragma unroll
        for (int ns = 0; ns < 4; ns++) {
            int col = n0 + wn + ns * 8 + (lane & 3) * 2;
            if (r0 < NN)
                *(unsigned int*)(g_h1 + (size_t)r0 * DHID + col) =
                    bf2(c[ms][ns][0], c[ms][ns][1]);
            if (r1 < NN)
                *(unsigned int*)(g_h1 + (size_t)r1 * DHID + col) =
                    bf2(c[ms][ns][2], c[ms][ns][3]);
        }
    }
}

// ---------------- GEMM 2 (tensor core, row-range): h2 = a1 @ W2 --------------
#define BP2 72
extern "C" __global__ __launch_bounds__(128) void k_gemm2(
    const float* __restrict__ B, int mbase) {
    __shared__ __align__(16) __nv_bfloat16 Asm[128 * AP1];
    __shared__ __align__(16) __nv_bfloat16 Bsm[16 * BP2];
    const int tid  = threadIdx.x;
    const int wid  = tid >> 5;
    const int lane = tid & 31;
    const int m0   = mbase + blockIdx.x * 128;
    const int wm   = (wid & 1) * 64;
    const int wn   = (wid >> 1) * 32;

    float c[4][4][4];
#pragma unroll
    for (int i = 0; i < 4; i++)
#pragma unroll
        for (int j = 0; j < 4; j++)
#pragma unroll
            for (int q = 0; q < 4; q++) c[i][j][q] = 0.f;

    for (int k0 = 0; k0 < DHID; k0 += 16) {
#pragma unroll
        for (int i = 0; i < 2; i++) {
            int idx  = tid + i * 128;
            int row  = idx >> 1;
            int half = (idx & 1) * 8;
            int gm   = m0 + row;
            uint4 v = make_uint4(0u, 0u, 0u, 0u);
            if (gm < NN) v = *(const uint4*)(g_a1 + (size_t)gm * DHID + k0 + half);
            *(uint4*)&Asm[row * AP1 + half] = v;
        }
#pragma unroll
        for (int i = 0; i < 2; i++) {
            int idx = tid + i * 128;
            int kr  = idx >> 4;
            int nc  = (idx & 15) * 4;
            float4 v = *(const float4*)(B + (size_t)(k0 + kr) * DOUT + nc);
            *(uint2*)&Bsm[kr * BP2 + nc] = make_uint2(bf2(v.x, v.y), bf2(v.z, v.w));
        }
        __syncthreads();

        unsigned int a[4][4];
#pragma unroll
        for (int ms = 0; ms < 4; ms++) {
            int row = wm + ms * 16 + (lane & 15);
            int col = (lane >> 4) * 8;
            ldsm_x4(smem_u32(&Asm[row * AP1 + col]),
                    a[ms][0], a[ms][1], a[ms][2], a[ms][3]);
        }
        unsigned int b[4][2];
#pragma unroll
        for (int nt = 0; nt < 2; nt++) {
            int k  = lane & 15;
            int nb = wn + nt * 16 + (lane >> 4) * 8;
            ldsm_x4t(smem_u32(&Bsm[k * BP2 + nb]),
                     b[2 * nt][0], b[2 * nt][1], b[2 * nt + 1][0], b[2 * nt + 1][1]);
        }
#pragma unroll
        for (int ms = 0; ms < 4; ms++)
#pragma unroll
            for (int ns = 0; ns < 4; ns++)
                mma_bf16(c[ms][ns], a[ms][0], a[ms][1], a[ms][2], a[ms][3],
                         b[ns][0], b[ns][1]);
        __syncthreads();
    }
#pragma unroll
    for (int ms = 0; ms < 4; ms++) {
        int r0 = m0 + wm + ms * 16 + (lane >> 2);
        int r1 = r0 + 8;
#pragma unroll
        for (int ns = 0; ns < 4; ns++) {
            int col = wn + ns * 8 + (lane & 3) * 2;
            if (r0 < NN)
                *(unsigned int*)(g_h2 + (size_t)r0 * DOUT + col) =
                    bf2(c[ms][ns][0], c[ms][ns][1]);
            if (r1 < NN)
                *(unsigned int*)(g_h2 + (size_t)r1 * DOUT + col) =
                    bf2(c[ms][ns][2], c[ms][ns][3]);
        }
    }
}

// ---------------- layer-1 aggregation (node range), unroll-8 ------------------
__device__ __forceinline__ void acc_row1(float acc[8], float ws, uint4 v) {
    const unsigned int* u = (const unsigned int*)&v;
#pragma unroll
    for (int q = 0; q < 4; q++) {
        float2 f = ubf2f(u[q]);
        acc[2 * q]     = fmaf(ws, f.x, acc[2 * q]);
        acc[2 * q + 1] = fmaf(ws, f.y, acc[2 * q + 1]);
    }
}

extern "C" __global__ __launch_bounds__(256) void k_agg1(const float* __restrict__ b1,
                                                         int lo, int hi) {
    int lane = threadIdx.x & 31;
    int w = lo + ((blockIdx.x * blockDim.x + threadIdx.x) >> 5);
    if (w >= hi) return;
    {
        float di = g_dinv[w];
        float acc[8];
        {
            uint4 v = __ldg(&((const uint4*)(g_h1 + (size_t)w * DHID))[lane]);
            const unsigned int* u = (const unsigned int*)&v;
#pragma unroll
            for (int q = 0; q < 4; q++) {
                float2 f = ubf2f(u[q]);
                acc[2 * q]     = di * f.x;
                acc[2 * q + 1] = di * f.y;
            }
        }
        int e   = g_off[w];
        int end = g_off[w + 1];
        for (; e + 8 <= end; e += 8) {
            int s0 = __ldg(&g_csr[e]);
            int s1 = __ldg(&g_csr[e + 1]);
            int s2 = __ldg(&g_csr[e + 2]);
            int s3 = __ldg(&g_csr[e + 3]);
            int s4 = __ldg(&g_csr[e + 4]);
            int s5 = __ldg(&g_csr[e + 5]);
            int s6 = __ldg(&g_csr[e + 6]);
            int s7 = __ldg(&g_csr[e + 7]);
            float w0 = __ldg(&g_dinv[s0]);
            float w1 = __ldg(&g_dinv[s1]);
            float w2 = __ldg(&g_dinv[s2]);
            float w3 = __ldg(&g_dinv[s3]);
            float w4 = __ldg(&g_dinv[s4]);
            float w5 = __ldg(&g_dinv[s5]);
            float w6 = __ldg(&g_dinv[s6]);
            float w7 = __ldg(&g_dinv[s7]);
            uint4 v0 = __ldg(&((const uint4*)(g_h1 + (size_t)s0 * DHID))[lane]);
            uint4 v1 = __ldg(&((const uint4*)(g_h1 + (size_t)s1 * DHID))[lane]);
            uint4 v2 = __ldg(&((const uint4*)(g_h1 + (size_t)s2 * DHID))[lane]);
            uint4 v3 = __ldg(&((const uint4*)(g_h1 + (size_t)s3 * DHID))[lane]);
            uint4 v4 = __ldg(&((const uint4*)(g_h1 + (size_t)s4 * DHID))[lane]);
            uint4 v5 = __ldg(&((const uint4*)(g_h1 + (size_t)s5 * DHID))[lane]);
            uint4 v6 = __ldg(&((const uint4*)(g_h1 + (size_t)s6 * DHID))[lane]);
            uint4 v7 = __ldg(&((const uint4*)(g_h1 + (size_t)s7 * DHID))[lane]);
            acc_row1(acc, w0, v0);
            acc_row1(acc, w1, v1);
            acc_row1(acc, w2, v2);
            acc_row1(acc, w3, v3);
            acc_row1(acc, w4, v4);
            acc_row1(acc, w5, v5);
            acc_row1(acc, w6, v6);
            acc_row1(acc, w7, v7);
        }
        for (; e + 4 <= end; e += 4) {
            int s0 = __ldg(&g_csr[e]);
            int s1 = __ldg(&g_csr[e + 1]);
            int s2 = __ldg(&g_csr[e + 2]);
            int s3 = __ldg(&g_csr[e + 3]);
            float w0 = __ldg(&g_dinv[s0]);
            float w1 = __ldg(&g_dinv[s1]);
            float w2 = __ldg(&g_dinv[s2]);
            float w3 = __ldg(&g_dinv[s3]);
            uint4 v0 = __ldg(&((const uint4*)(g_h1 + (size_t)s0 * DHID))[lane]);
            uint4 v1 = __ldg(&((const uint4*)(g_h1 + (size_t)s1 * DHID))[lane]);
            uint4 v2 = __ldg(&((const uint4*)(g_h1 + (size_t)s2 * DHID))[lane]);
            uint4 v3 = __ldg(&((const uint4*)(g_h1 + (size_t)s3 * DHID))[lane]);
            acc_row1(acc, w0, v0);
            acc_row1(acc, w1, v1);
            acc_row1(acc, w2, v2);
            acc_row1(acc, w3, v3);
        }
        for (; e < end; e++) {
            int   s  = __ldg(&g_csr[e]);
            float ws = __ldg(&g_dinv[s]);
            uint4 v  = __ldg(&((const uint4*)(g_h1 + (size_t)s * DHID))[lane]);
            acc_row1(acc, ws, v);
        }
        float4 bb0 = ((const float4*)b1)[lane * 2];
        float4 bb1 = ((const float4*)b1)[lane * 2 + 1];
        uint4 pk;
        pk.x = bf2(fmaxf(di * acc[0] + bb0.x, 0.f), fmaxf(di * acc[1] + bb0.y, 0.f));
        pk.y = bf2(fmaxf(di * acc[2] + bb0.z, 0.f), fmaxf(di * acc[3] + bb0.w, 0.f));
        pk.z = bf2(fmaxf(di * acc[4] + bb1.x, 0.f), fmaxf(di * acc[5] + bb1.y, 0.f));
        pk.w = bf2(fmaxf(di * acc[6] + bb1.z, 0.f), fmaxf(di * acc[7] + bb1.w, 0.f));
        ((uint4*)(g_a1 + (size_t)w * DHID))[lane] = pk;
    }
}

// ---------------- layer-2 aggregation + bias + log_softmax, unroll-8 ---------
extern "C" __global__ __launch_bounds__(256) void k_agg2(const float* __restrict__ b2,
                                                         float* __restrict__ out) {
    int lane = threadIdx.x & 31;
    int warps = (gridDim.x * blockDim.x) >> 5;
    for (int w = (blockIdx.x * blockDim.x + threadIdx.x) >> 5; w < NN; w += warps) {
        float di = g_dinv[w];
        float ax, ay;
        {
            unsigned int v = __ldg(&((const unsigned int*)(g_h2 + (size_t)w * DOUT))[lane]);
            float2 f = ubf2f(v);
            ax = di * f.x;
            ay = di * f.y;
        }
        int e   = g_off[w];
        int end = g_off[w + 1];
        for (; e + 8 <= end; e += 8) {
            int s0 = __ldg(&g_csr[e]);
            int s1 = __ldg(&g_csr[e + 1]);
            int s2 = __ldg(&g_csr[e + 2]);
            int s3 = __ldg(&g_csr[e + 3]);
            int s4 = __ldg(&g_csr[e + 4]);
            int s5 = __ldg(&g_csr[e + 5]);
            int s6 = __ldg(&g_csr[e + 6]);
            int s7 = __ldg(&g_csr[e + 7]);
            float w0 = __ldg(&g_dinv[s0]);
            float w1 = __ldg(&g_dinv[s1]);
            float w2 = __ldg(&g_dinv[s2]);
            float w3 = __ldg(&g_dinv[s3]);
            float w4 = __ldg(&g_dinv[s4]);
            float w5 = __ldg(&g_dinv[s5]);
            float w6 = __ldg(&g_dinv[s6]);
            float w7 = __ldg(&g_dinv[s7]);
            unsigned int v0 = __ldg(&((const unsigned int*)(g_h2 + (size_t)s0 * DOUT))[lane]);
            unsigned int v1 = __ldg(&((const unsigned int*)(g_h2 + (size_t)s1 * DOUT))[lane]);
            unsigned int v2 = __ldg(&((const unsigned int*)(g_h2 + (size_t)s2 * DOUT))[lane]);
            unsigned int v3 = __ldg(&((const unsigned int*)(g_h2 + (size_t)s3 * DOUT))[lane]);
            unsigned int v4 = __ldg(&((const unsigned int*)(g_h2 + (size_t)s4 * DOUT))[lane]);
            unsigned int v5 = __ldg(&((const unsigned int*)(g_h2 + (size_t)s5 * DOUT))[lane]);
            unsigned int v6 = __ldg(&((const unsigned int*)(g_h2 + (size_t)s6 * DOUT))[lane]);
            unsigned int v7 = __ldg(&((const unsigned int*)(g_h2 + (size_t)s7 * DOUT))[lane]);
            float2 f0 = ubf2f(v0), f1 = ubf2f(v1), f2 = ubf2f(v2), f3 = ubf2f(v3);
            float2 f4 = ubf2f(v4), f5 = ubf2f(v5), f6 = ubf2f(v6), f7 = ubf2f(v7);
            ax = fmaf(w0, f0.x, ax); ay = fmaf(w0, f0.y, ay);
            ax = fmaf(w1, f1.x, ax); ay = fmaf(w1, f1.y, ay);
            ax = fmaf(w2, f2.x, ax); ay = fmaf(w2, f2.y, ay);
            ax = fmaf(w3, f3.x, ax); ay = fmaf(w3, f3.y, ay);
            ax = fmaf(w4, f4.x, ax); ay = fmaf(w4, f4.y, ay);
            ax = fmaf(w5, f5.x, ax); ay = fmaf(w5, f5.y, ay);
            ax = fmaf(w6, f6.x, ax); ay = fmaf(w6, f6.y, ay);
            ax = fmaf(w7, f7.x, ax); ay = fmaf(w7, f7.y, ay);
        }
        for (; e < end; e++) {
            int   s  = __ldg(&g_csr[e]);
            float ws = __ldg(&g_dinv[s]);
            unsigned int v = __ldg(&((const unsigned int*)(g_h2 + (size_t)s * DOUT))[lane]);
            float2 f = ubf2f(v);
            ax = fmaf(ws, f.x, ax);
            ay = fmaf(ws, f.y, ay);
        }
        float2 bb = ((const float2*)b2)[lane];
        float zx = di * ax + bb.x;
        float zy = di * ay + bb.y;
        float m = fmaxf(zx, zy);
#pragma unroll
        for (int o = 16; o; o >>= 1) m = fmaxf(m, __shfl_xor_sync(0xffffffffu, m, o));
        float s = expf(zx - m) + expf(zy - m);
#pragma unroll
        for (int o = 16; o; o >>= 1) s += __shfl_xor_sync(0xffffffffu, s, o);
        float lse = m + logf(s);
        float2 r; r.x = zx - lse; r.y = zy - lse;
        ((float2*)(out + (size_t)w * DOUT))[lane] = r;
    }
}

// ---------------- launch ------------------------------------------------------
extern "C" void kernel_launch(void* const* d_in, const int* in_sizes, int n_in,
                              void* d_out, int out_size) {
    const float* x  = nullptr;
    const int*   ei = nullptr;
    const float* W1 = nullptr;
    const float* b1 = nullptr;
    const float* W2 = nullptr;
    const float* b2 = nullptr;
    for (int i = 0; i < n_in; i++) {
        switch (in_sizes[i]) {
            case NN * DIN:    x  = (const float*)d_in[i]; break;
            case 2 * EE:      ei = (const int*)d_in[i];   break;
            case DIN * DHID:  W1 = (const float*)d_in[i]; break;
            case DHID:        b1 = (const float*)d_in[i]; break;
            case DHID * DOUT: W2 = (const float*)d_in[i]; break;
            case DOUT:        b2 = (const float*)d_in[i]; break;
            default: break;
        }
    }
    float* out = (float*)d_out;
    const int* src = ei;
    const int* dst = ei + EE;

    int* p_deg;  cudaGetSymbolAddress((void**)&p_deg, g_deg);

    // fork: x->bf16 + gemm1 on side stream; CSR build on main stream
    cudaEventRecord(g_evA, 0);
    cudaStreamWaitEvent(g_s2, g_evA, 0);
    k_cvt<<<2048, 256, 0, g_s2>>>(x);
    k_gemm1<<<2 * ((NN + 127) / 128), 256, 0, g_s2>>>(W1);
    cudaEventRecord(g_evB, g_s2);

    cudaMemsetAsync(p_deg, 0, NN * sizeof(int));
    k_count<<<2048, 256>>>(dst, EE);
    k_blksum<<<NB2, 512>>>();
    k_offsets<<<NB2, 512>>>();
    k_fill<<<2048, 256>>>(src, dst, EE);

    // join: agg1 needs gemm1 (h1) + CSR
    cudaStreamWaitEvent(0, g_evB, 0);

    // agg1 first half, then overlap gemm2(first half) with agg1(second half)
    k_agg1<<<(SPLIT + 7) / 8, 256>>>(b1, 0, SPLIT);
    cudaEventRecord(g_evC, 0);
    cudaStreamWaitEvent(g_s2, g_evC, 0);
    k_gemm2<<<SPLIT / 128, 128, 0, g_s2>>>(W2, 0);
    cudaEventRecord(g_evD, g_s2);

    k_agg1<<<(NN - SPLIT + 7) / 8, 256>>>(b1, SPLIT, NN);
    k_gemm2<<<(NN - SPLIT + 127) / 128, 128>>>(W2, SPLIT);

    // join gemm2 halves, then final aggregation + log-softmax
    cudaStreamWaitEvent(0, g_evD, 0);
    k_agg2<<<12500, 256>>>(b2, out);
}